// round 13
// baseline (speedup 1.0000x reference)
#include <cuda_runtime.h>
#include <cstdint>

// Problem constants (fixed shapes per reference)
#define N_SAMPLES 8192
#define I_BLOCK   128                 // threads per CTA
#define IPT       4                   // a-points per thread (register tile)
#define I_TILE    (I_BLOCK * IPT)     // 512 a-points per CTA
#define K_CHUNK   64                  // b-points per CTA chunk
#define N_IBLK    (N_SAMPLES / I_TILE)    // 16
#define N_KBLK    (N_SAMPLES / K_CHUNK)   // 128
#define N_CTAS    (N_IBLK * N_KBLK)       // 2048

// Scratch (no allocations). Zero-initialized at module load (.bss); the last
// CTA of every launch resets them to zero again -> every replay identical.
__device__ unsigned g_key[N_SAMPLES];     // complemented monotone keys (0 = empty)
__device__ float    g_sqa_part[N_IBLK];   // per-i-block sum of ||a||^2
__device__ unsigned g_done;               // completion counter

// Packed f32x2 FMA (Blackwell FFMA2) — only reachable via PTX.
#define FMA2(d, a, b, c) \
    asm("fma.rn.f32x2 %0, %1, %2, %3;" : "=l"(d) : "l"(a), "l"(b), "l"(c))
#define PACK2(d, f) \
    asm("mov.b64 %0, {%1, %1};" : "=l"(d) : "f"(f))
#define UNPACK2(lo, hi, v) \
    asm("mov.b64 {%0, %1}, %2;" : "=f"(lo), "=f"(hi) : "l"(v))

// Monotone uint key for float (total order matches float <, incl. negatives)
__device__ __forceinline__ unsigned fkey(float f) {
    unsigned u = __float_as_uint(f);
    return (u & 0x80000000u) ? ~u : (u | 0x80000000u);
}
__device__ __forceinline__ float funkey(unsigned k) {
    unsigned u = (k & 0x80000000u) ? (k & 0x7FFFFFFFu) : ~k;
    return __uint_as_float(u);
}

// ---------------------------------------------------------------------------
// Single fused kernel. grid = (16 i-blocks, 128 k-chunks) = 2048 CTAs, 128 thr.
//  1. Gather own 64-pt b-chunk (global->smem SoA) and own 4 a-points.
//  2. kblk==0 CTAs also produce deterministic ||a||^2 partial sums.
//  3. Main loop: 4 b-pts/iter via packed FFMA2, scalar FMNMX min chains.
//  4. Merge mins via atomicMax on complemented keys (REDG.MAX, empty=0).
//  5. Last-finishing CTA: decode+sum -> out[0], then reset keys/counter.
// ---------------------------------------------------------------------------
__global__ void __launch_bounds__(I_BLOCK)
chamfer_fused_kernel(const float* __restrict__ a,
                     const float* __restrict__ b,
                     const int* __restrict__ a_idx,
                     const int* __restrict__ b_idx,
                     int n_points,
                     float* __restrict__ out) {
    __shared__ float s[4 * K_CHUNK];          // 1 KB, SoA b-chunk
    __shared__ float red[I_BLOCK / 32];
    __shared__ unsigned s_islast;

    const int t = threadIdx.x;
    const int kbase = blockIdx.y * K_CHUNK;
    const int ibase = blockIdx.x * I_TILE;

    // --- gather b-chunk into smem (warps 0-1) ---
    if (t < K_CHUNK) {
        int kb = b_idx[kbase + t];
        float bx = b[kb];
        float by = b[n_points + kb];
        float bz = b[2 * n_points + kb];
        s[0 * K_CHUNK + t] = -2.0f * bx;
        s[1 * K_CHUNK + t] = -2.0f * by;
        s[2 * K_CHUNK + t] = -2.0f * bz;
        s[3 * K_CHUNK + t] = bx * bx + by * by + bz * bz;
    }

    // --- gather own 4 a-points (coalesced idx, scattered component loads) ---
    float ax[IPT], ay[IPT], az[IPT];
    #pragma unroll
    for (int j = 0; j < IPT; ++j) {
        int ia = a_idx[ibase + j * I_BLOCK + t];
        ax[j] = a[ia];
        ay[j] = a[n_points + ia];
        az[j] = a[2 * n_points + ia];
    }

    // --- ||a||^2 partial sums (only the 16 kblk==0 CTAs; deterministic) ---
    if (blockIdx.y == 0) {
        float sq = 0.0f;
        #pragma unroll
        for (int j = 0; j < IPT; ++j)
            sq += ax[j] * ax[j] + ay[j] * ay[j] + az[j] * az[j];
        #pragma unroll
        for (int off = 16; off > 0; off >>= 1)
            sq += __shfl_down_sync(0xFFFFFFFFu, sq, off);
        if ((t & 31) == 0) red[t >> 5] = sq;
    }
    __syncthreads();
    if (blockIdx.y == 0 && t == 0)
        g_sqa_part[blockIdx.x] = red[0] + red[1] + red[2] + red[3];

    // --- pack a-coords for FFMA2 ---
    unsigned long long pax2[IPT], pay2[IPT], paz2[IPT];
    #pragma unroll
    for (int j = 0; j < IPT; ++j) {
        PACK2(pax2[j], ax[j]);
        PACK2(pay2[j], ay[j]);
        PACK2(paz2[j], az[j]);
    }

    const longlong2* xs = (const longlong2*)(s);
    const longlong2* ys = (const longlong2*)(s + K_CHUNK);
    const longlong2* zs = (const longlong2*)(s + 2 * K_CHUNK);
    const longlong2* ws = (const longlong2*)(s + 3 * K_CHUNK);

    float mA[IPT], mB[IPT];
    #pragma unroll
    for (int j = 0; j < IPT; ++j) { mA[j] = 3.4e38f; mB[j] = 3.4e38f; }

    #pragma unroll 4
    for (int g = 0; g < K_CHUNK / 4; ++g) {
        longlong2 X = xs[g];   // 4 consecutive -2bx values (2 packed f32x2)
        longlong2 Y = ys[g];
        longlong2 Z = zs[g];
        longlong2 W = ws[g];

        #pragma unroll
        for (int j = 0; j < IPT; ++j) {
            unsigned long long v01, v23;
            FMA2(v01, X.x, pax2[j], W.x);
            FMA2(v23, X.y, pax2[j], W.y);
            FMA2(v01, Y.x, pay2[j], v01);
            FMA2(v23, Y.y, pay2[j], v23);
            FMA2(v01, Z.x, paz2[j], v01);
            FMA2(v23, Z.y, paz2[j], v23);

            float a0, a1, a2, a3;
            UNPACK2(a0, a1, v01);
            UNPACK2(a2, a3, v23);
            mA[j] = fminf(mA[j], fminf(a0, a1));
            mB[j] = fminf(mB[j], fminf(a2, a3));
        }
    }

    // min over floats == max over complemented keys; empty slot = 0.
    #pragma unroll
    for (int j = 0; j < IPT; ++j) {
        float m = fminf(mA[j], mB[j]);
        atomicMax(&g_key[ibase + j * I_BLOCK + t], ~fkey(m));  // -> REDG.MAX
    }

    // ---- completion counter: last CTA reduces, writes out, resets state ----
    __threadfence();
    __syncthreads();
    if (t == 0) {
        unsigned c = atomicAdd(&g_done, 1u);
        s_islast = (c == (unsigned)(N_CTAS - 1)) ? 1u : 0u;
    }
    __syncthreads();
    if (!s_islast) return;

    __threadfence();  // acquire: all REDG.MAX results + sqa partials visible

    float sum = (t < N_IBLK) ? ((const volatile float*)g_sqa_part)[t] : 0.0f;
    for (int j = t; j < N_SAMPLES; j += I_BLOCK) {
        unsigned kk = ((const volatile unsigned*)g_key)[j];  // bypass L1
        sum += funkey(~kk);
        g_key[j] = 0u;   // reset for next replay
    }
    // warp reduce
    #pragma unroll
    for (int off = 16; off > 0; off >>= 1)
        sum += __shfl_down_sync(0xFFFFFFFFu, sum, off);
    if ((t & 31) == 0) red[t >> 5] = sum;
    __syncthreads();
    if (t == 0) {
        out[0] = red[0] + red[1] + red[2] + red[3];
        g_done = 0u;     // reset counter for next replay
    }
}

// ---------------------------------------------------------------------------
extern "C" void kernel_launch(void* const* d_in, const int* in_sizes, int n_in,
                              void* d_out, int out_size) {
    const float* a     = (const float*)d_in[0];
    const float* b     = (const float*)d_in[1];
    const int*   a_idx = (const int*)d_in[2];
    const int*   b_idx = (const int*)d_in[3];
    float* out = (float*)d_out;

    int n_points = in_sizes[0] / 3;   // 16384

    chamfer_fused_kernel<<<dim3(N_IBLK, N_KBLK), I_BLOCK>>>(
        a, b, a_idx, b_idx, n_points, out);
}

// round 14
// speedup vs baseline: 1.2911x; 1.2911x over previous
#include <cuda_runtime.h>
#include <cstdint>

// Problem constants (fixed shapes per reference)
#define N_SAMPLES 8192
#define I_BLOCK   128                 // threads per CTA
#define IPT       4                   // a-points per thread (register tile)
#define I_TILE    (I_BLOCK * IPT)     // 512 a-points per CTA
#define K_CHUNK   128                 // b-points per CTA chunk
#define N_IBLK    (N_SAMPLES / I_TILE)    // 16
#define N_KBLK    (N_SAMPLES / K_CHUNK)   // 64
#define N_CTAS    (N_IBLK * N_KBLK)       // 1024  (~one resident wave)

// Scratch (no allocations allowed).
// g_soa layout: [0..8191]=-2bx, [8192..]=-2by, [16384..]=-2bz, [24576..]=||b||^2
__device__ float    g_soa[4 * N_SAMPLES];
__device__ float4   g_pa[N_SAMPLES];     // (ax, ay, az, ||a||^2)
__device__ unsigned g_minkey[N_SAMPLES];
__device__ unsigned g_done;

// Packed f32x2 FMA (Blackwell FFMA2) — only reachable via PTX.
#define FMA2(d, a, b, c) \
    asm("fma.rn.f32x2 %0, %1, %2, %3;" : "=l"(d) : "l"(a), "l"(b), "l"(c))
#define PACK2(d, f) \
    asm("mov.b64 %0, {%1, %1};" : "=l"(d) : "f"(f))
#define UNPACK2(lo, hi, v) \
    asm("mov.b64 {%0, %1}, %2;" : "=f"(lo), "=f"(hi) : "l"(v))

// Monotone uint key for float (total order matches float <, incl. negatives)
__device__ __forceinline__ unsigned fkey(float f) {
    unsigned u = __float_as_uint(f);
    return (u & 0x80000000u) ? ~u : (u | 0x80000000u);
}
__device__ __forceinline__ float funkey(unsigned k) {
    unsigned u = (k & 0x80000000u) ? (k & 0x7FFFFFFFu) : ~k;
    return __uint_as_float(u);
}

// ---------------------------------------------------------------------------
// Kernel 1: gather sampled points into SoA form, init min keys + done counter.
// 256 CTAs x 32 threads: spread scattered LDGs across many SMs/L1tex queues.
// ---------------------------------------------------------------------------
__global__ void gather_init_kernel(const float* __restrict__ a,
                                   const float* __restrict__ b,
                                   const int* __restrict__ a_idx,
                                   const int* __restrict__ b_idx,
                                   int n_points) {
    int i = blockIdx.x * blockDim.x + threadIdx.x;
    if (i >= N_SAMPLES) return;
    if (i == 0) g_done = 0u;

    int ia = a_idx[i];
    float ax = a[ia];
    float ay = a[n_points + ia];
    float az = a[2 * n_points + ia];
    g_pa[i] = make_float4(ax, ay, az, ax * ax + ay * ay + az * az);

    int ib = b_idx[i];
    float bx = b[ib];
    float by = b[n_points + ib];
    float bz = b[2 * n_points + ib];
    // v(i,k) = ||b_k||^2 - 2 * dot(b_k, a_i)
    g_soa[0 * N_SAMPLES + i] = -2.0f * bx;
    g_soa[1 * N_SAMPLES + i] = -2.0f * by;
    g_soa[2 * N_SAMPLES + i] = -2.0f * bz;
    g_soa[3 * N_SAMPLES + i] = bx * bx + by * by + bz * bz;

    g_minkey[i] = 0xFFFFFFFFu;  // +max key
}

// ---------------------------------------------------------------------------
// Kernel 2: main pass + fused final reduction (R12 mix, single-wave grid).
// grid = (16 i-blocks, 64 k-chunks) = 1024 CTAs, 128 threads, ~8 CTAs/SM ->
// the whole grid is one resident wave (no ragged wave-2 tail).
// Each thread owns FOUR a-points; inner loop processes 4 b-points via packed
// FFMA2; mins accumulate via scalar FMNMX into 8 independent chains.
// Per 16 pairs: 4 LDS.128 + 24 FFMA2 + 16 FMNMX.
// atomicMin with unused return -> REDG.MIN (fire-and-forget).
// Last-finishing CTA performs the decode+sum.
// ---------------------------------------------------------------------------
__global__ void __launch_bounds__(I_BLOCK)
chamfer_min_kernel(float* __restrict__ out) {
    __shared__ float s[4 * K_CHUNK];          // 2 KB, SoA chunk
    __shared__ float warp_sums[I_BLOCK / 32];
    __shared__ unsigned s_islast;

    const int t = threadIdx.x;
    const int kbase = blockIdx.y * K_CHUNK;
    const int ibase = blockIdx.x * I_TILE;

    // Cooperative chunk load: 128 float4 total (every thread loads one).
    {
        int c = t >> 5;          // component (32 float4 per component)
        int j = t & 31;
        ((float4*)(s + c * K_CHUNK))[j] =
            ((const float4*)(g_soa + c * N_SAMPLES + kbase))[j];
    }

    // Load 4 a-points (coalesced: stride I_BLOCK) — overlaps with chunk load
    float4 pa[IPT];
    #pragma unroll
    for (int j = 0; j < IPT; ++j) pa[j] = g_pa[ibase + j * I_BLOCK + t];
    __syncthreads();

    unsigned long long pax2[IPT], pay2[IPT], paz2[IPT];
    #pragma unroll
    for (int j = 0; j < IPT; ++j) {
        PACK2(pax2[j], pa[j].x);
        PACK2(pay2[j], pa[j].y);
        PACK2(paz2[j], pa[j].z);
    }

    const longlong2* xs = (const longlong2*)(s);
    const longlong2* ys = (const longlong2*)(s + K_CHUNK);
    const longlong2* zs = (const longlong2*)(s + 2 * K_CHUNK);
    const longlong2* ws = (const longlong2*)(s + 3 * K_CHUNK);

    float mA[IPT], mB[IPT];
    #pragma unroll
    for (int j = 0; j < IPT; ++j) { mA[j] = 3.4e38f; mB[j] = 3.4e38f; }

    #pragma unroll 4
    for (int g = 0; g < K_CHUNK / 4; ++g) {
        longlong2 X = xs[g];   // 4 consecutive -2bx values (2 packed f32x2)
        longlong2 Y = ys[g];
        longlong2 Z = zs[g];
        longlong2 W = ws[g];

        #pragma unroll
        for (int j = 0; j < IPT; ++j) {
            unsigned long long v01, v23;
            FMA2(v01, X.x, pax2[j], W.x);
            FMA2(v23, X.y, pax2[j], W.y);
            FMA2(v01, Y.x, pay2[j], v01);
            FMA2(v23, Y.y, pay2[j], v23);
            FMA2(v01, Z.x, paz2[j], v01);
            FMA2(v23, Z.y, paz2[j], v23);

            float a0, a1, a2, a3;
            UNPACK2(a0, a1, v01);
            UNPACK2(a2, a3, v23);
            mA[j] = fminf(mA[j], fminf(a0, a1));
            mB[j] = fminf(mB[j], fminf(a2, a3));
        }
    }

    #pragma unroll
    for (int j = 0; j < IPT; ++j) {
        float m = fminf(mA[j], mB[j]);
        atomicMin(&g_minkey[ibase + j * I_BLOCK + t], fkey(m));  // -> REDG.MIN
    }

    // ---- completion counter: last CTA does the final reduction ----
    __threadfence();
    __syncthreads();
    if (t == 0) {
        unsigned c = atomicAdd(&g_done, 1u);
        s_islast = (c == (unsigned)(N_CTAS - 1)) ? 1u : 0u;
    }
    __syncthreads();
    if (!s_islast) return;

    __threadfence();  // acquire: all REDG.MIN results now visible

    float sum = 0.0f;
    for (int j = t; j < N_SAMPLES; j += I_BLOCK) {
        unsigned kk = ((const volatile unsigned*)g_minkey)[j];  // bypass L1
        sum += g_pa[j].w + funkey(kk);
    }
    // warp reduce
    #pragma unroll
    for (int off = 16; off > 0; off >>= 1)
        sum += __shfl_down_sync(0xFFFFFFFFu, sum, off);
    if ((t & 31) == 0) warp_sums[t >> 5] = sum;
    __syncthreads();
    if (t == 0)
        out[0] = warp_sums[0] + warp_sums[1] + warp_sums[2] + warp_sums[3];
}

// ---------------------------------------------------------------------------
extern "C" void kernel_launch(void* const* d_in, const int* in_sizes, int n_in,
                              void* d_out, int out_size) {
    const float* a     = (const float*)d_in[0];
    const float* b     = (const float*)d_in[1];
    const int*   a_idx = (const int*)d_in[2];
    const int*   b_idx = (const int*)d_in[3];
    float* out = (float*)d_out;

    int n_points = in_sizes[0] / 3;   // 16384

    gather_init_kernel<<<256, 32>>>(a, b, a_idx, b_idx, n_points);
    chamfer_min_kernel<<<dim3(N_IBLK, N_KBLK), I_BLOCK>>>(out);
}

// round 15
// speedup vs baseline: 1.4484x; 1.1218x over previous
#include <cuda_runtime.h>
#include <cstdint>

// Problem constants (fixed shapes per reference)
#define N_SAMPLES 8192
#define I_BLOCK   128                 // threads per CTA
#define IPT       8                   // a-points per thread (register tile)
#define I_TILE    (I_BLOCK * IPT)     // 1024 a-points per CTA
#define K_CHUNK   32                  // b-points per CTA chunk
#define N_IBLK    (N_SAMPLES / I_TILE)    // 8
#define N_KBLK    (N_SAMPLES / K_CHUNK)   // 256
#define N_CTAS    (N_IBLK * N_KBLK)       // 2048

// Scratch (no allocations allowed).
// g_soa layout: [0..8191]=-2bx, [8192..]=-2by, [16384..]=-2bz, [24576..]=||b||^2
__device__ float    g_soa[4 * N_SAMPLES];
__device__ float4   g_pa[N_SAMPLES];      // (ax, ay, az, ||a||^2)
__device__ unsigned g_minkey[N_SAMPLES];
__device__ unsigned g_done_blk[N_IBLK];   // per-i-block completion counters
__device__ float    g_psum[N_IBLK];       // per-i-block partial sums
__device__ unsigned g_done;               // global completion counter

// Packed f32x2 FMA (Blackwell FFMA2) — only reachable via PTX.
#define FMA2(d, a, b, c) \
    asm("fma.rn.f32x2 %0, %1, %2, %3;" : "=l"(d) : "l"(a), "l"(b), "l"(c))
#define PACK2(d, f) \
    asm("mov.b64 %0, {%1, %1};" : "=l"(d) : "f"(f))
#define UNPACK2(lo, hi, v) \
    asm("mov.b64 {%0, %1}, %2;" : "=f"(lo), "=f"(hi) : "l"(v))

// Monotone uint key for float (total order matches float <, incl. negatives)
__device__ __forceinline__ unsigned fkey(float f) {
    unsigned u = __float_as_uint(f);
    return (u & 0x80000000u) ? ~u : (u | 0x80000000u);
}
__device__ __forceinline__ float funkey(unsigned k) {
    unsigned u = (k & 0x80000000u) ? (k & 0x7FFFFFFFu) : ~k;
    return __uint_as_float(u);
}

// ---------------------------------------------------------------------------
// Kernel 1: gather sampled points into SoA form, init min keys + counters.
// 256 CTAs x 32 threads: spread scattered LDGs across many SMs/L1tex queues.
// ---------------------------------------------------------------------------
__global__ void gather_init_kernel(const float* __restrict__ a,
                                   const float* __restrict__ b,
                                   const int* __restrict__ a_idx,
                                   const int* __restrict__ b_idx,
                                   int n_points) {
    int i = blockIdx.x * blockDim.x + threadIdx.x;
    if (i >= N_SAMPLES) return;
    if (i == 0) g_done = 0u;
    if (i < N_IBLK) g_done_blk[i] = 0u;

    int ia = a_idx[i];
    float ax = a[ia];
    float ay = a[n_points + ia];
    float az = a[2 * n_points + ia];
    g_pa[i] = make_float4(ax, ay, az, ax * ax + ay * ay + az * az);

    int ib = b_idx[i];
    float bx = b[ib];
    float by = b[n_points + ib];
    float bz = b[2 * n_points + ib];
    // v(i,k) = ||b_k||^2 - 2 * dot(b_k, a_i)
    g_soa[0 * N_SAMPLES + i] = -2.0f * bx;
    g_soa[1 * N_SAMPLES + i] = -2.0f * by;
    g_soa[2 * N_SAMPLES + i] = -2.0f * bz;
    g_soa[3 * N_SAMPLES + i] = bx * bx + by * by + bz * bz;

    g_minkey[i] = 0xFFFFFFFFu;  // +max key
}

// ---------------------------------------------------------------------------
// Kernel 2: main pass + hierarchical fused reduction.
// grid = (8 i-blocks, 256 k-chunks) = 2048 CTAs, 128 threads.
// Each thread owns EIGHT a-points; inner loop processes 4 b-points via packed
// FFMA2. Per 32 pairs: 4 LDS.128 + 48 FFMA2 + 32 FMNMX (~3.2 issues/pair).
// atomicMin with unused return -> REDG.MIN (fire-and-forget).
// Last k-CTA of each i-block reduces its 1024 mins -> g_psum[iblk];
// globally-last CTA's thread 0 sums the 8 partials -> out[0].
// ---------------------------------------------------------------------------
__global__ void __launch_bounds__(I_BLOCK)
chamfer_min_kernel(float* __restrict__ out) {
    __shared__ float s[4 * K_CHUNK];          // 512 B, SoA chunk
    __shared__ float warp_sums[I_BLOCK / 32];
    __shared__ unsigned s_islast;

    const int t = threadIdx.x;
    const int kbase = blockIdx.y * K_CHUNK;
    const int ibase = blockIdx.x * I_TILE;

    // Cooperative chunk load: 32 float4 total (threads 0..31, one each).
    if (t < 32) {
        int c = t >> 3;          // component (8 float4 per component)
        int j = t & 7;
        ((float4*)(s + c * K_CHUNK))[j] =
            ((const float4*)(g_soa + c * N_SAMPLES + kbase))[j];
    }

    // Load 8 a-points (coalesced: stride I_BLOCK) — overlaps with chunk load
    float4 pa[IPT];
    #pragma unroll
    for (int j = 0; j < IPT; ++j) pa[j] = g_pa[ibase + j * I_BLOCK + t];
    __syncthreads();

    unsigned long long pax2[IPT], pay2[IPT], paz2[IPT];
    #pragma unroll
    for (int j = 0; j < IPT; ++j) {
        PACK2(pax2[j], pa[j].x);
        PACK2(pay2[j], pa[j].y);
        PACK2(paz2[j], pa[j].z);
    }

    const longlong2* xs = (const longlong2*)(s);
    const longlong2* ys = (const longlong2*)(s + K_CHUNK);
    const longlong2* zs = (const longlong2*)(s + 2 * K_CHUNK);
    const longlong2* ws = (const longlong2*)(s + 3 * K_CHUNK);

    float mA[IPT], mB[IPT];
    #pragma unroll
    for (int j = 0; j < IPT; ++j) { mA[j] = 3.4e38f; mB[j] = 3.4e38f; }

    #pragma unroll 2
    for (int g = 0; g < K_CHUNK / 4; ++g) {
        longlong2 X = xs[g];   // 4 consecutive -2bx values (2 packed f32x2)
        longlong2 Y = ys[g];
        longlong2 Z = zs[g];
        longlong2 W = ws[g];

        #pragma unroll
        for (int j = 0; j < IPT; ++j) {
            unsigned long long v01, v23;
            FMA2(v01, X.x, pax2[j], W.x);
            FMA2(v23, X.y, pax2[j], W.y);
            FMA2(v01, Y.x, pay2[j], v01);
            FMA2(v23, Y.y, pay2[j], v23);
            FMA2(v01, Z.x, paz2[j], v01);
            FMA2(v23, Z.y, paz2[j], v23);

            float a0, a1, a2, a3;
            UNPACK2(a0, a1, v01);
            UNPACK2(a2, a3, v23);
            mA[j] = fminf(mA[j], fminf(a0, a1));
            mB[j] = fminf(mB[j], fminf(a2, a3));
        }
    }

    #pragma unroll
    for (int j = 0; j < IPT; ++j) {
        float m = fminf(mA[j], mB[j]);
        atomicMin(&g_minkey[ibase + j * I_BLOCK + t], fkey(m));  // -> REDG.MIN
    }

    // ---- stage 1: per-i-block completion; last k-CTA reduces its block ----
    __threadfence();
    __syncthreads();
    if (t == 0) {
        unsigned c = atomicAdd(&g_done_blk[blockIdx.x], 1u);
        s_islast = (c == (unsigned)(N_KBLK - 1)) ? 1u : 0u;
    }
    __syncthreads();
    if (!s_islast) return;

    __threadfence();  // acquire: all REDG.MIN results for this i-block visible

    float sum = 0.0f;
    #pragma unroll
    for (int j = 0; j < IPT; ++j) {
        int idx = ibase + j * I_BLOCK + t;
        unsigned kk = ((const volatile unsigned*)g_minkey)[idx];  // bypass L1
        sum += pa[j].w + funkey(kk);
    }
    // CTA reduce
    #pragma unroll
    for (int off = 16; off > 0; off >>= 1)
        sum += __shfl_down_sync(0xFFFFFFFFu, sum, off);
    if ((t & 31) == 0) warp_sums[t >> 5] = sum;
    __syncthreads();

    // ---- stage 2: global completion; last CTA's thread 0 sums partials ----
    if (t == 0) {
        g_psum[blockIdx.x] =
            warp_sums[0] + warp_sums[1] + warp_sums[2] + warp_sums[3];
        __threadfence();
        unsigned c = atomicAdd(&g_done, 1u);
        if (c == (unsigned)(N_IBLK - 1)) {
            float total = 0.0f;
            #pragma unroll
            for (int i = 0; i < N_IBLK; ++i)
                total += ((const volatile float*)g_psum)[i];
            out[0] = total;
        }
    }
}

// ---------------------------------------------------------------------------
extern "C" void kernel_launch(void* const* d_in, const int* in_sizes, int n_in,
                              void* d_out, int out_size) {
    const float* a     = (const float*)d_in[0];
    const float* b     = (const float*)d_in[1];
    const int*   a_idx = (const int*)d_in[2];
    const int*   b_idx = (const int*)d_in[3];
    float* out = (float*)d_out;

    int n_points = in_sizes[0] / 3;   // 16384

    gather_init_kernel<<<256, 32>>>(a, b, a_idx, b_idx, n_points);
    chamfer_min_kernel<<<dim3(N_IBLK, N_KBLK), I_BLOCK>>>(out);
}